// round 6
// baseline (speedup 1.0000x reference)
#include <cuda_runtime.h>
#include <cuda_bf16.h>
#include <cstdint>

#define BATCH   4096
#define INF     8192
#define OUTF    8192
#define NGRP    1024
#define WLEN    (NGRP * INF)

#define NCHUNK  64
#define RPC     (BATCH / NCHUNK)   // 64 rows per chunk

// Scratch (allocation-free rule: __device__ globals)
__device__ float g_partial[NCHUNK * INF];   // 2 MB
__device__ float g_s;

// ---------------------------------------------------------------------------
// K1: partial column sums. grid = (8, NCHUNK), block = 256 threads.
// Each thread owns one float4 column group (4 cols) within one 64-row chunk,
// with 8 rows in flight for MLP.
// ---------------------------------------------------------------------------
__global__ void __launch_bounds__(256) colsum_kernel(const float* __restrict__ x) {
    const int chunk = blockIdx.y;
    const int c4 = blockIdx.x * blockDim.x + threadIdx.x;      // 0..2047
    const size_t row_stride4 = INF / 4;                        // 2048
    const float4* __restrict__ xp =
        reinterpret_cast<const float4*>(x) + (size_t)chunk * RPC * row_stride4 + c4;

    float4 a0 = {0.f,0.f,0.f,0.f};
    float4 a1 = {0.f,0.f,0.f,0.f};
    float4 a2 = {0.f,0.f,0.f,0.f};
    float4 a3 = {0.f,0.f,0.f,0.f};

    #pragma unroll 2
    for (int r = 0; r < RPC; r += 8) {
        float4 v0 = xp[(size_t)(r + 0) * row_stride4];
        float4 v1 = xp[(size_t)(r + 1) * row_stride4];
        float4 v2 = xp[(size_t)(r + 2) * row_stride4];
        float4 v3 = xp[(size_t)(r + 3) * row_stride4];
        float4 v4 = xp[(size_t)(r + 4) * row_stride4];
        float4 v5 = xp[(size_t)(r + 5) * row_stride4];
        float4 v6 = xp[(size_t)(r + 6) * row_stride4];
        float4 v7 = xp[(size_t)(r + 7) * row_stride4];
        a0.x += v0.x; a0.y += v0.y; a0.z += v0.z; a0.w += v0.w;
        a1.x += v1.x; a1.y += v1.y; a1.z += v1.z; a1.w += v1.w;
        a2.x += v2.x; a2.y += v2.y; a2.z += v2.z; a2.w += v2.w;
        a3.x += v3.x; a3.y += v3.y; a3.z += v3.z; a3.w += v3.w;
        a0.x += v4.x; a0.y += v4.y; a0.z += v4.z; a0.w += v4.w;
        a1.x += v5.x; a1.y += v5.y; a1.z += v5.z; a1.w += v5.w;
        a2.x += v6.x; a2.y += v6.y; a2.z += v6.z; a2.w += v6.w;
        a3.x += v7.x; a3.y += v7.y; a3.z += v7.z; a3.w += v7.w;
    }
    float4 out;
    out.x = (a0.x + a1.x) + (a2.x + a3.x);
    out.y = (a0.y + a1.y) + (a2.y + a3.y);
    out.z = (a0.z + a1.z) + (a2.z + a3.z);
    out.w = (a0.w + a1.w) + (a2.w + a3.w);
    reinterpret_cast<float4*>(g_partial)[(size_t)chunk * row_stride4 + c4] = out;
}

// ---------------------------------------------------------------------------
// K2: single block (1024 threads). Finish the reduction, do the group logic,
// produce scalar s.
// ---------------------------------------------------------------------------
__global__ void __launch_bounds__(1024) scalar_kernel(
    const float* __restrict__ wflat,
    const float* __restrict__ mins,
    const float* __restrict__ maxs,
    const int*   __restrict__ start_pos,
    const int*   __restrict__ offsets,
    const int*   __restrict__ sizes)
{
    __shared__ float smins[NGRP];
    __shared__ float red[1024];
    const int t = threadIdx.x;
    smins[t] = mins[t];              // NGRP == blockDim == 1024
    __syncthreads();

    float acc = 0.f;
    #pragma unroll
    for (int c = 0; c < INF / 1024; c++) {
        const int j = c * 1024 + t;
        float sum = 0.f;
        #pragma unroll 8
        for (int k = 0; k < NCHUNK; k++)
            sum += g_partial[(size_t)k * INF + j];
        const float val = sum * (1.0f / (float)BATCH);

        // searchsorted(mins, val, side='right') - 1
        int lo = 0, hi = NGRP;
        while (lo < hi) {
            int mid = (lo + hi) >> 1;
            if (smins[mid] <= val) lo = mid + 1; else hi = mid;
        }
        const int g  = lo - 1;
        const int gc = min(max(g, 0), NGRP - 1);
        const bool hit = (g >= 0) && (val >= smins[gc]) && (val <= maxs[gc]);
        const int pos = j - start_pos[gc];
        const bool pos_ok = (pos >= 0) && (pos < sizes[gc]);

        float w = 0.f;
        if (hit && pos_ok) {
            long long idx = (long long)offsets[gc] + (long long)pos;
            idx = idx < 0 ? 0 : idx;
            idx = idx > (long long)(WLEN - 1) ? (long long)(WLEN - 1) : idx;
            w = wflat[idx];
        }
        acc += val * w;
    }

    red[t] = acc;
    __syncthreads();
    #pragma unroll
    for (int sft = 512; sft > 0; sft >>= 1) {
        if (t < sft) red[t] += red[t + sft];
        __syncthreads();
    }
    if (t == 0) g_s = red[0];
}

// ---------------------------------------------------------------------------
// K3: row 0 only (8192 floats). Bulk zeros handled by cudaMemsetAsync.
// out_mask is a JAX bool delivered as int32.
// ---------------------------------------------------------------------------
__global__ void __launch_bounds__(256) row0_kernel(
    float* __restrict__ out, const int* __restrict__ mask)
{
    const int i4 = blockIdx.x * blockDim.x + threadIdx.x;   // 0..2047
    const float s = g_s;
    const int j = i4 * 4;
    float4 v;
    v.x = (mask[j + 0] != 0) ? s : 0.f;
    v.y = (mask[j + 1] != 0) ? s : 0.f;
    v.z = (mask[j + 2] != 0) ? s : 0.f;
    v.w = (mask[j + 3] != 0) ? s : 0.f;
    reinterpret_cast<float4*>(out)[i4] = v;
}

// ---------------------------------------------------------------------------
extern "C" void kernel_launch(void* const* d_in, const int* in_sizes, int n_in,
                              void* d_out, int out_size)
{
    const float* x         = (const float*)d_in[0];
    const float* wflat     = (const float*)d_in[1];
    const float* mins      = (const float*)d_in[2];
    const float* maxs      = (const float*)d_in[3];
    const int*   start_pos = (const int*)d_in[4];
    const int*   offsets   = (const int*)d_in[5];
    const int*   sizes     = (const int*)d_in[6];
    const int*   out_mask  = (const int*)d_in[7];
    float*       out       = (float*)d_out;

    // Bulk zero of the whole 128 MB output (graph-capturable memset node).
    cudaMemsetAsync(out, 0, (size_t)BATCH * OUTF * sizeof(float), 0);

    // K1: (8 col-blocks of 1024 cols) x (64 row-chunks of 64 rows)
    dim3 g1(8, NCHUNK);
    colsum_kernel<<<g1, 256>>>(x);

    // K2: scalar
    scalar_kernel<<<1, 1024>>>(wflat, mins, maxs, start_pos, offsets, sizes);

    // K3: overwrite row 0 (runs after memset + K2 in stream order)
    row0_kernel<<<OUTF / 4 / 256, 256>>>(out, out_mask);
}

// round 10
// speedup vs baseline: 1.3000x; 1.3000x over previous
#include <cuda_runtime.h>
#include <cuda_bf16.h>
#include <cstdint>

#define BATCH   4096
#define INF     8192
#define OUTF    8192
#define NGRP    1024
#define WLEN    (NGRP * INF)

#define NCHUNK  64
#define RPC     (BATCH / NCHUNK)   // 64 rows per chunk

// Scratch (allocation-free rule: __device__ globals)
__device__ float g_partial[NCHUNK * INF];   // 2 MB
__device__ float g_val[INF];                // 32 KB column means

// ---------------------------------------------------------------------------
// K1: partial column sums. grid = (8, NCHUNK), block = 256 threads.
// ---------------------------------------------------------------------------
__global__ void __launch_bounds__(256) colsum_kernel(const float* __restrict__ x) {
    const int chunk = blockIdx.y;
    const int c4 = blockIdx.x * blockDim.x + threadIdx.x;      // 0..2047
    const size_t row_stride4 = INF / 4;                        // 2048
    const float4* __restrict__ xp =
        reinterpret_cast<const float4*>(x) + (size_t)chunk * RPC * row_stride4 + c4;

    float4 a0 = {0.f,0.f,0.f,0.f};
    float4 a1 = {0.f,0.f,0.f,0.f};
    float4 a2 = {0.f,0.f,0.f,0.f};
    float4 a3 = {0.f,0.f,0.f,0.f};

    #pragma unroll 2
    for (int r = 0; r < RPC; r += 8) {
        float4 v0 = xp[(size_t)(r + 0) * row_stride4];
        float4 v1 = xp[(size_t)(r + 1) * row_stride4];
        float4 v2 = xp[(size_t)(r + 2) * row_stride4];
        float4 v3 = xp[(size_t)(r + 3) * row_stride4];
        float4 v4 = xp[(size_t)(r + 4) * row_stride4];
        float4 v5 = xp[(size_t)(r + 5) * row_stride4];
        float4 v6 = xp[(size_t)(r + 6) * row_stride4];
        float4 v7 = xp[(size_t)(r + 7) * row_stride4];
        a0.x += v0.x; a0.y += v0.y; a0.z += v0.z; a0.w += v0.w;
        a1.x += v1.x; a1.y += v1.y; a1.z += v1.z; a1.w += v1.w;
        a2.x += v2.x; a2.y += v2.y; a2.z += v2.z; a2.w += v2.w;
        a3.x += v3.x; a3.y += v3.y; a3.z += v3.z; a3.w += v3.w;
        a0.x += v4.x; a0.y += v4.y; a0.z += v4.z; a0.w += v4.w;
        a1.x += v5.x; a1.y += v5.y; a1.z += v5.z; a1.w += v5.w;
        a2.x += v6.x; a2.y += v6.y; a2.z += v6.z; a2.w += v6.w;
        a3.x += v7.x; a3.y += v7.y; a3.z += v7.z; a3.w += v7.w;
    }
    float4 out;
    out.x = (a0.x + a1.x) + (a2.x + a3.x);
    out.y = (a0.y + a1.y) + (a2.y + a3.y);
    out.z = (a0.z + a1.z) + (a2.z + a3.z);
    out.w = (a0.w + a1.w) + (a2.w + a3.w);
    reinterpret_cast<float4*>(g_partial)[(size_t)chunk * row_stride4 + c4] = out;
}

// ---------------------------------------------------------------------------
// K2a: parallel final reduction. 32 blocks x 256 threads, one column each.
// Reads the 2 MB partials across many SMs (L2-resident), writes val[8192].
// ---------------------------------------------------------------------------
__global__ void __launch_bounds__(256) reduce_kernel() {
    const int j = blockIdx.x * blockDim.x + threadIdx.x;   // 0..8191
    float s0 = 0.f, s1 = 0.f, s2 = 0.f, s3 = 0.f;
    #pragma unroll 4
    for (int k = 0; k < NCHUNK; k += 4) {
        s0 += g_partial[(size_t)(k + 0) * INF + j];
        s1 += g_partial[(size_t)(k + 1) * INF + j];
        s2 += g_partial[(size_t)(k + 2) * INF + j];
        s3 += g_partial[(size_t)(k + 3) * INF + j];
    }
    g_val[j] = ((s0 + s1) + (s2 + s3)) * (1.0f / (float)BATCH);
}

// ---------------------------------------------------------------------------
// K2b: single block (1024 threads). searchsorted + masked dot on val (32 KB,
// L2-resident), block-reduce to s, then write masked row 0 of the output.
// out_mask is a JAX bool delivered as int32.
// ---------------------------------------------------------------------------
__global__ void __launch_bounds__(1024) scalar_row0_kernel(
    const float* __restrict__ wflat,
    const float* __restrict__ mins,
    const float* __restrict__ maxs,
    const int*   __restrict__ start_pos,
    const int*   __restrict__ offsets,
    const int*   __restrict__ sizes,
    const int*   __restrict__ mask,
    float*       __restrict__ out)
{
    __shared__ float smins[NGRP];
    __shared__ float red[1024];
    const int t = threadIdx.x;
    smins[t] = mins[t];              // NGRP == blockDim == 1024
    __syncthreads();

    float acc = 0.f;
    #pragma unroll
    for (int c = 0; c < INF / 1024; c++) {
        const int j = c * 1024 + t;
        const float val = g_val[j];

        // searchsorted(mins, val, side='right') - 1
        int lo = 0, hi = NGRP;
        while (lo < hi) {
            int mid = (lo + hi) >> 1;
            if (smins[mid] <= val) lo = mid + 1; else hi = mid;
        }
        const int g  = lo - 1;
        const int gc = min(max(g, 0), NGRP - 1);
        const bool hit = (g >= 0) && (val >= smins[gc]) && (val <= maxs[gc]);
        const int pos = j - start_pos[gc];
        const bool pos_ok = (pos >= 0) && (pos < sizes[gc]);

        float w = 0.f;
        if (hit && pos_ok) {
            long long idx = (long long)offsets[gc] + (long long)pos;
            idx = idx < 0 ? 0 : idx;
            idx = idx > (long long)(WLEN - 1) ? (long long)(WLEN - 1) : idx;
            w = wflat[idx];
        }
        acc += val * w;
    }

    red[t] = acc;
    __syncthreads();
    #pragma unroll
    for (int sft = 512; sft > 0; sft >>= 1) {
        if (t < sft) red[t] += red[t + sft];
        __syncthreads();
    }
    const float s = red[0];   // valid in all threads after last __syncthreads

    // Write masked row 0: 8192 floats = 2048 float4 groups, 2 per thread.
    #pragma unroll
    for (int c = 0; c < OUTF / 4 / 1024; c++) {
        const int i4 = c * 1024 + t;
        const int j = i4 * 4;
        float4 v;
        v.x = (mask[j + 0] != 0) ? s : 0.f;
        v.y = (mask[j + 1] != 0) ? s : 0.f;
        v.z = (mask[j + 2] != 0) ? s : 0.f;
        v.w = (mask[j + 3] != 0) ? s : 0.f;
        reinterpret_cast<float4*>(out)[i4] = v;
    }
}

// ---------------------------------------------------------------------------
extern "C" void kernel_launch(void* const* d_in, const int* in_sizes, int n_in,
                              void* d_out, int out_size)
{
    const float* x         = (const float*)d_in[0];
    const float* wflat     = (const float*)d_in[1];
    const float* mins      = (const float*)d_in[2];
    const float* maxs      = (const float*)d_in[3];
    const int*   start_pos = (const int*)d_in[4];
    const int*   offsets   = (const int*)d_in[5];
    const int*   sizes     = (const int*)d_in[6];
    const int*   out_mask  = (const int*)d_in[7];
    float*       out       = (float*)d_out;

    // Bulk zero of the whole 128 MB output (graph-capturable memset node).
    cudaMemsetAsync(out, 0, (size_t)BATCH * OUTF * sizeof(float), 0);

    // K1: (8 col-blocks of 1024 cols) x (64 row-chunks of 64 rows)
    dim3 g1(8, NCHUNK);
    colsum_kernel<<<g1, 256>>>(x);

    // K2a: parallel reduction of partials -> val
    reduce_kernel<<<INF / 256, 256>>>();

    // K2b: scalar + masked row 0 (after memset in stream order)
    scalar_row0_kernel<<<1, 1024>>>(wflat, mins, maxs, start_pos, offsets,
                                    sizes, out_mask, out);
}

// round 11
// speedup vs baseline: 1.3195x; 1.0150x over previous
#include <cuda_runtime.h>
#include <cuda_bf16.h>
#include <cstdint>

#define BATCH   4096
#define INF     8192
#define OUTF    8192
#define NGRP    1024
#define WLEN    (NGRP * INF)

#define NCHUNK  64
#define RPC     (BATCH / NCHUNK)   // 64 rows per chunk

// Scratch (allocation-free rule: __device__ globals)
__device__ float g_partial[NCHUNK * INF];   // 2 MB
__device__ float g_val[INF];                // 32 KB column means

// ---------------------------------------------------------------------------
// K1: fused zero-fill + partial column sums. grid = (8, NCHUNK) = 512 blocks,
// 256 threads. Each block: (a) zero-fills its 256 KB slice of out (stores are
// fire-and-forget), (b) computes its 64-row x 1024-col partial column sums.
// Read and write DRAM streams proceed concurrently inside one kernel.
// ---------------------------------------------------------------------------
__global__ void __launch_bounds__(256) colsum_zero_kernel(
    const float* __restrict__ x, float* __restrict__ out)
{
    const int chunk = blockIdx.y;
    const int bid   = blockIdx.y * gridDim.x + blockIdx.x;     // 0..511
    const int c4    = blockIdx.x * blockDim.x + threadIdx.x;   // 0..2047
    const size_t row_stride4 = INF / 4;                        // 2048

    // --- (a) zero-fill slice: 8M float4 total / 512 blocks = 16384 per block
    {
        const float4 z = {0.f, 0.f, 0.f, 0.f};
        float4* __restrict__ o4 =
            reinterpret_cast<float4*>(out) + (size_t)bid * 16384 + threadIdx.x;
        #pragma unroll 8
        for (int i = 0; i < 64; i++)
            o4[(size_t)i * 256] = z;
    }

    // --- (b) partial column sums
    const float4* __restrict__ xp =
        reinterpret_cast<const float4*>(x) + (size_t)chunk * RPC * row_stride4 + c4;

    float4 a0 = {0.f,0.f,0.f,0.f};
    float4 a1 = {0.f,0.f,0.f,0.f};
    float4 a2 = {0.f,0.f,0.f,0.f};
    float4 a3 = {0.f,0.f,0.f,0.f};

    #pragma unroll 2
    for (int r = 0; r < RPC; r += 8) {
        float4 v0 = xp[(size_t)(r + 0) * row_stride4];
        float4 v1 = xp[(size_t)(r + 1) * row_stride4];
        float4 v2 = xp[(size_t)(r + 2) * row_stride4];
        float4 v3 = xp[(size_t)(r + 3) * row_stride4];
        float4 v4 = xp[(size_t)(r + 4) * row_stride4];
        float4 v5 = xp[(size_t)(r + 5) * row_stride4];
        float4 v6 = xp[(size_t)(r + 6) * row_stride4];
        float4 v7 = xp[(size_t)(r + 7) * row_stride4];
        a0.x += v0.x; a0.y += v0.y; a0.z += v0.z; a0.w += v0.w;
        a1.x += v1.x; a1.y += v1.y; a1.z += v1.z; a1.w += v1.w;
        a2.x += v2.x; a2.y += v2.y; a2.z += v2.z; a2.w += v2.w;
        a3.x += v3.x; a3.y += v3.y; a3.z += v3.z; a3.w += v3.w;
        a0.x += v4.x; a0.y += v4.y; a0.z += v4.z; a0.w += v4.w;
        a1.x += v5.x; a1.y += v5.y; a1.z += v5.z; a1.w += v5.w;
        a2.x += v6.x; a2.y += v6.y; a2.z += v6.z; a2.w += v6.w;
        a3.x += v7.x; a3.y += v7.y; a3.z += v7.z; a3.w += v7.w;
    }
    float4 ps;
    ps.x = (a0.x + a1.x) + (a2.x + a3.x);
    ps.y = (a0.y + a1.y) + (a2.y + a3.y);
    ps.z = (a0.z + a1.z) + (a2.z + a3.z);
    ps.w = (a0.w + a1.w) + (a2.w + a3.w);
    reinterpret_cast<float4*>(g_partial)[(size_t)chunk * row_stride4 + c4] = ps;
}

// ---------------------------------------------------------------------------
// K2a: parallel final reduction. 32 blocks x 256 threads, one column each.
// ---------------------------------------------------------------------------
__global__ void __launch_bounds__(256) reduce_kernel() {
    const int j = blockIdx.x * blockDim.x + threadIdx.x;   // 0..8191
    float s0 = 0.f, s1 = 0.f, s2 = 0.f, s3 = 0.f;
    #pragma unroll 4
    for (int k = 0; k < NCHUNK; k += 4) {
        s0 += g_partial[(size_t)(k + 0) * INF + j];
        s1 += g_partial[(size_t)(k + 1) * INF + j];
        s2 += g_partial[(size_t)(k + 2) * INF + j];
        s3 += g_partial[(size_t)(k + 3) * INF + j];
    }
    g_val[j] = ((s0 + s1) + (s2 + s3)) * (1.0f / (float)BATCH);
}

// ---------------------------------------------------------------------------
// K2b: single block (1024 threads). searchsorted + masked dot on val (32 KB,
// L2-resident), block-reduce to s, then write masked row 0 of the output.
// out_mask is a JAX bool delivered as int32.
// ---------------------------------------------------------------------------
__global__ void __launch_bounds__(1024) scalar_row0_kernel(
    const float* __restrict__ wflat,
    const float* __restrict__ mins,
    const float* __restrict__ maxs,
    const int*   __restrict__ start_pos,
    const int*   __restrict__ offsets,
    const int*   __restrict__ sizes,
    const int*   __restrict__ mask,
    float*       __restrict__ out)
{
    __shared__ float smins[NGRP];
    __shared__ float red[1024];
    const int t = threadIdx.x;
    smins[t] = mins[t];              // NGRP == blockDim == 1024
    __syncthreads();

    float acc = 0.f;
    #pragma unroll
    for (int c = 0; c < INF / 1024; c++) {
        const int j = c * 1024 + t;
        const float val = g_val[j];

        // searchsorted(mins, val, side='right') - 1
        int lo = 0, hi = NGRP;
        while (lo < hi) {
            int mid = (lo + hi) >> 1;
            if (smins[mid] <= val) lo = mid + 1; else hi = mid;
        }
        const int g  = lo - 1;
        const int gc = min(max(g, 0), NGRP - 1);
        const bool hit = (g >= 0) && (val >= smins[gc]) && (val <= maxs[gc]);
        const int pos = j - start_pos[gc];
        const bool pos_ok = (pos >= 0) && (pos < sizes[gc]);

        float w = 0.f;
        if (hit && pos_ok) {
            long long idx = (long long)offsets[gc] + (long long)pos;
            idx = idx < 0 ? 0 : idx;
            idx = idx > (long long)(WLEN - 1) ? (long long)(WLEN - 1) : idx;
            w = wflat[idx];
        }
        acc += val * w;
    }

    red[t] = acc;
    __syncthreads();
    #pragma unroll
    for (int sft = 512; sft > 0; sft >>= 1) {
        if (t < sft) red[t] += red[t + sft];
        __syncthreads();
    }
    const float s = red[0];   // valid in all threads after last __syncthreads

    // Write masked row 0: 8192 floats = 2048 float4 groups, 2 per thread.
    #pragma unroll
    for (int c = 0; c < OUTF / 4 / 1024; c++) {
        const int i4 = c * 1024 + t;
        const int j = i4 * 4;
        float4 v;
        v.x = (mask[j + 0] != 0) ? s : 0.f;
        v.y = (mask[j + 1] != 0) ? s : 0.f;
        v.z = (mask[j + 2] != 0) ? s : 0.f;
        v.w = (mask[j + 3] != 0) ? s : 0.f;
        reinterpret_cast<float4*>(out)[i4] = v;
    }
}

// ---------------------------------------------------------------------------
extern "C" void kernel_launch(void* const* d_in, const int* in_sizes, int n_in,
                              void* d_out, int out_size)
{
    const float* x         = (const float*)d_in[0];
    const float* wflat     = (const float*)d_in[1];
    const float* mins      = (const float*)d_in[2];
    const float* maxs      = (const float*)d_in[3];
    const int*   start_pos = (const int*)d_in[4];
    const int*   offsets   = (const int*)d_in[5];
    const int*   sizes     = (const int*)d_in[6];
    const int*   out_mask  = (const int*)d_in[7];
    float*       out       = (float*)d_out;

    // K1: fused zero-fill + column partial sums
    dim3 g1(8, NCHUNK);
    colsum_zero_kernel<<<g1, 256>>>(x, out);

    // K2a: parallel reduction of partials -> val
    reduce_kernel<<<INF / 256, 256>>>();

    // K2b: scalar + masked row 0 (after K1's zero-fill in stream order)
    scalar_row0_kernel<<<1, 1024>>>(wflat, mins, maxs, start_pos, offsets,
                                    sizes, out_mask, out);
}